// round 1
// baseline (speedup 1.0000x reference)
#include <cuda_runtime.h>

#define Bv 4
#define Nv 256
#define Dv 256
#define Ev 256
#define Mv (Bv*Nv*Nv)     // 262144 pair rows
#define BIv (Bv*Nv)       // 1024 (b,i) rows

// scratch (no allocations allowed)
__device__ __align__(16) float g_s12[BIv * 512];     // s1 (cols 0..255), s2+b_in (cols 256..511)
__device__ __align__(16) float g_coef[2 * Mv];       // per-col-tile partial coef sums
__device__ __align__(16) float g_resid[BIv * Dv];

// ---------------------------------------------------------------------------
// s12: [1024,256] (nodes) @ W_in[0:512,:] -> g_s12 [1024,512]
// BM=64, BN=64, BK=16, 256 threads, 4x4 per thread
__global__ void k_s12(const float* __restrict__ nodes, const float* __restrict__ Win,
                      const float* __restrict__ b_in) {
    __shared__ float As[16][64];
    __shared__ float Bs[16][64];
    int tid = threadIdx.x;
    int tx = tid & 15, ty = tid >> 4;
    int row0 = blockIdx.x * 64;
    int n0   = blockIdx.y * 64;
    float c[4][4] = {};
    for (int k0 = 0; k0 < 256; k0 += 16) {
        {
            int r = tid >> 2, kq = tid & 3;
            float4 v = *(const float4*)&nodes[(size_t)(row0 + r) * 256 + k0 + kq * 4];
            As[kq*4+0][r] = v.x; As[kq*4+1][r] = v.y; As[kq*4+2][r] = v.z; As[kq*4+3][r] = v.w;
        }
        {
            int k = tid >> 4, nq = tid & 15;
            int n = n0 + nq * 4;
            const float* src = (n < 256) ? &Win[(size_t)(k0 + k) * 256 + n]
                                         : &Win[(size_t)(256 + k0 + k) * 256 + (n - 256)];
            *(float4*)&Bs[k][nq*4] = *(const float4*)src;
        }
        __syncthreads();
#pragma unroll
        for (int k = 0; k < 16; k++) {
            float a[4], b[4];
            *(float4*)a = *(float4*)&As[k][ty*4];
            *(float4*)b = *(float4*)&Bs[k][tx*4];
#pragma unroll
            for (int i = 0; i < 4; i++)
#pragma unroll
                for (int j = 0; j < 4; j++) c[i][j] += a[i] * b[j];
        }
        __syncthreads();
    }
#pragma unroll
    for (int i = 0; i < 4; i++) {
        int row = row0 + ty*4 + i;
#pragma unroll
        for (int j = 0; j < 4; j++) {
            int n = n0 + tx*4 + j;
            float v = c[i][j] + (n >= 256 ? b_in[n - 256] : 0.f);
            g_s12[(size_t)row * 512 + n] = v;
        }
    }
}

// ---------------------------------------------------------------------------
// main: cat = relu(edges @ W3 + s1[b,i] + s2[b,j]); coef partials fused.
// BM=128, BN=128, BK=16, 256 threads, 8x8 per thread. grid (2048, 2)
__global__ void k_main(const float* __restrict__ edges, const float* __restrict__ Win,
                       const float* __restrict__ Wcoef, float* __restrict__ cat) {
    __shared__ float As[16][128];
    __shared__ float Bs[16][128];
    __shared__ float wcs[128];
    __shared__ float red[128][17];
    int tid = threadIdx.x;
    int tx = tid & 15, ty = tid >> 4;
    int row0 = blockIdx.x * 128;
    int n0   = blockIdx.y * 128;
    int bi = row0 >> 8;          // all 128 rows in the tile share (b,i)
    int b  = bi >> 8;

    if (tid < 128) wcs[tid] = Wcoef[n0 + tid];

    float c[8][8] = {};
    for (int k0 = 0; k0 < 256; k0 += 16) {
#pragma unroll
        for (int l = tid; l < 512; l += 256) {
            int r = l >> 2, kq = l & 3;
            float4 v = *(const float4*)&edges[(size_t)(row0 + r) * 256 + k0 + kq * 4];
            As[kq*4+0][r] = v.x; As[kq*4+1][r] = v.y; As[kq*4+2][r] = v.z; As[kq*4+3][r] = v.w;
        }
#pragma unroll
        for (int l = tid; l < 512; l += 256) {
            int k = l >> 5, nq = l & 31;
            *(float4*)&Bs[k][nq*4] = *(const float4*)&Win[(size_t)(512 + k0 + k) * 256 + n0 + nq * 4];
        }
        __syncthreads();
#pragma unroll
        for (int k = 0; k < 16; k++) {
            float a[8], bb[8];
            *(float4*)&a[0]  = *(float4*)&As[k][ty*8];
            *(float4*)&a[4]  = *(float4*)&As[k][ty*8+4];
            *(float4*)&bb[0] = *(float4*)&Bs[k][tx*8];
            *(float4*)&bb[4] = *(float4*)&Bs[k][tx*8+4];
#pragma unroll
            for (int i = 0; i < 8; i++)
#pragma unroll
                for (int j = 0; j < 8; j++) c[i][j] += a[i] * bb[j];
        }
        __syncthreads();
    }

    // epilogue: add s1/s2, relu, store cat, accumulate coef partials
    float s1f[8];
    {
        const float* s1p = &g_s12[(size_t)bi * 512 + n0 + tx * 8];
#pragma unroll
        for (int j = 0; j < 8; j++) s1f[j] = s1p[j];
    }
#pragma unroll
    for (int i = 0; i < 8; i++) {
        int m  = row0 + ty*8 + i;
        int jj = m & 255;                      // neighbor index j
        const float* s2p = &g_s12[((size_t)(b * 256 + jj)) * 512 + 256 + n0 + tx * 8];
        float out[8];
        float csum = 0.f;
#pragma unroll
        for (int j = 0; j < 8; j++) {
            float v = c[i][j] + s1f[j] + s2p[j];
            v = fmaxf(v, 0.f);
            out[j] = v;
            csum += v * wcs[tx*8 + j];
        }
        red[ty*8 + i][tx] = csum;   // stash per-row partial for this tx
        float* dst = &cat[(size_t)m * 256 + n0 + tx * 8];
        *(float4*)&dst[0] = *(float4*)&out[0];
        *(float4*)&dst[4] = *(float4*)&out[4];
    }
    __syncthreads();
    if (tid < 128) {
        float s = 0.f;
#pragma unroll
        for (int t = 0; t < 16; t++) s += red[tid][t];
        g_coef[(size_t)blockIdx.y * Mv + row0 + tid] = s;
    }
}

// ---------------------------------------------------------------------------
// softmax over neighbors + weighted sum -> g_resid. block = (b,i), 256 threads
__global__ void k_softmax(const float* __restrict__ aux, const float* __restrict__ bcoef,
                          const float* __restrict__ cat) {
    __shared__ float attn[256];
    __shared__ float redbuf[8];
    int bi = blockIdx.x;
    int tid = threadIdx.x;
    size_t row = (size_t)bi * 256 + tid;
    float logit = aux[row] + g_coef[row] + g_coef[Mv + row] + bcoef[0];

    float v = logit;
#pragma unroll
    for (int o = 16; o > 0; o >>= 1) v = fmaxf(v, __shfl_xor_sync(0xffffffffu, v, o));
    if ((tid & 31) == 0) redbuf[tid >> 5] = v;
    __syncthreads();
    float mx = redbuf[0];
#pragma unroll
    for (int i = 1; i < 8; i++) mx = fmaxf(mx, redbuf[i]);

    float e = expf(logit - mx);
    v = e;
#pragma unroll
    for (int o = 16; o > 0; o >>= 1) v += __shfl_xor_sync(0xffffffffu, v, o);
    __syncthreads();                 // redbuf reuse
    if ((tid & 31) == 0) redbuf[tid >> 5] = v;
    __syncthreads();
    float s = 0.f;
#pragma unroll
    for (int i = 0; i < 8; i++) s += redbuf[i];
    attn[tid] = e / s;
    __syncthreads();

    const float* cp = &cat[(size_t)bi * 65536 + tid];
    float acc = 0.f;
#pragma unroll 8
    for (int j = 0; j < 256; j++) acc += attn[j] * cp[(size_t)j * 256];
    g_resid[row] = acc;
}

// ---------------------------------------------------------------------------
// out: nodes + relu(resid @ W_out + b_out). BM=64 BN=64, grid (16,4)
__global__ void k_out(const float* __restrict__ nodes, const float* __restrict__ Wout,
                      const float* __restrict__ b_out, float* __restrict__ outn) {
    __shared__ float As[16][64];
    __shared__ float Bs[16][64];
    int tid = threadIdx.x;
    int tx = tid & 15, ty = tid >> 4;
    int row0 = blockIdx.x * 64;
    int n0   = blockIdx.y * 64;
    float c[4][4] = {};
    for (int k0 = 0; k0 < 256; k0 += 16) {
        {
            int r = tid >> 2, kq = tid & 3;
            float4 v = *(const float4*)&g_resid[(size_t)(row0 + r) * 256 + k0 + kq * 4];
            As[kq*4+0][r] = v.x; As[kq*4+1][r] = v.y; As[kq*4+2][r] = v.z; As[kq*4+3][r] = v.w;
        }
        {
            int k = tid >> 4, nq = tid & 15;
            *(float4*)&Bs[k][nq*4] = *(const float4*)&Wout[(size_t)(k0 + k) * 256 + n0 + nq * 4];
        }
        __syncthreads();
#pragma unroll
        for (int k = 0; k < 16; k++) {
            float a[4], b[4];
            *(float4*)a = *(float4*)&As[k][ty*4];
            *(float4*)b = *(float4*)&Bs[k][tx*4];
#pragma unroll
            for (int i = 0; i < 4; i++)
#pragma unroll
                for (int j = 0; j < 4; j++) c[i][j] += a[i] * b[j];
        }
        __syncthreads();
    }
#pragma unroll
    for (int i = 0; i < 4; i++) {
        int row = row0 + ty*4 + i;
#pragma unroll
        for (int j = 0; j < 4; j++) {
            int n = n0 + tx*4 + j;
            float v = fmaxf(c[i][j] + b_out[n], 0.f);
            outn[(size_t)row * 256 + n] = nodes[(size_t)row * 256 + n] + v;
        }
    }
}

// ---------------------------------------------------------------------------
extern "C" void kernel_launch(void* const* d_in, const int* in_sizes, int n_in,
                              void* d_out, int out_size) {
    const float* nodes = (const float*)d_in[0];
    const float* edges = (const float*)d_in[1];
    const float* aux   = (const float*)d_in[2];
    // d_in[3] = nums (unused)
    const float* Win   = (const float*)d_in[4];
    const float* b_in  = (const float*)d_in[5];
    const float* Wcoef = (const float*)d_in[6];
    const float* bcoef = (const float*)d_in[7];
    const float* Wout  = (const float*)d_in[8];
    const float* b_out = (const float*)d_in[9];

    float* out_nodes = (float*)d_out;                       // [4,256,256]
    float* out_cat   = out_nodes + (size_t)BIv * Dv;        // [4,256,256,256]

    k_s12    <<<dim3(16, 8),   256>>>(nodes, Win, b_in);
    k_main   <<<dim3(2048, 2), 256>>>(edges, Win, Wcoef, out_cat);
    k_softmax<<<1024,          256>>>(aux, bcoef, out_cat);
    k_out    <<<dim3(16, 4),   256>>>(nodes, Wout, b_out, out_nodes);
}

// round 3
// speedup vs baseline: 2.0917x; 2.0917x over previous
#include <cuda_runtime.h>
#include <cstdint>

#define Bv 4
#define Nv 256
#define Dv 256
#define Mv (Bv*Nv*Nv)     // 262144 pair rows
#define BIv (Bv*Nv)       // 1024 (b,i) rows

// scratch (no allocations allowed)
__device__ __align__(16) float g_s12[BIv * 512];     // s1 (cols 0..255), s2+b_in (cols 256..511)
__device__ __align__(16) float g_coef[2 * Mv];       // per-col-half coef partials
__device__ __align__(16) float g_resid[BIv * Dv];
__device__ __align__(16) float g_w3kn[256 * 256];    // W_in[512:768,:], tf32-rounded, [k][n]

__device__ __forceinline__ uint32_t f2tf32(float x) {
    uint32_t u; asm("cvt.rna.tf32.f32 %0, %1;" : "=r"(u) : "f"(x)); return u;
}
__device__ __forceinline__ uint32_t smem_u32(const void* p) {
    uint32_t a;
    asm("{ .reg .u64 t; cvta.to.shared.u64 t, %1; cvt.u32.u64 %0, t; }" : "=r"(a) : "l"(p));
    return a;
}
__device__ __forceinline__ void mma_tf32(float* d, const uint32_t* a, const uint32_t* b) {
    asm volatile(
        "mma.sync.aligned.m16n8k8.row.col.f32.tf32.tf32.f32 "
        "{%0,%1,%2,%3}, {%4,%5,%6,%7}, {%8,%9}, {%0,%1,%2,%3};"
        : "+f"(d[0]), "+f"(d[1]), "+f"(d[2]), "+f"(d[3])
        : "r"(a[0]), "r"(a[1]), "r"(a[2]), "r"(a[3]), "r"(b[0]), "r"(b[1]));
}
#define CP_ASYNC16(s, g) \
    asm volatile("cp.async.ca.shared.global [%0], [%1], 16;" :: "r"(s), "l"(g))
#define CP_COMMIT()  asm volatile("cp.async.commit_group;" ::: "memory")
#define CP_WAIT0()   asm volatile("cp.async.wait_group 0;" ::: "memory")

// ===========================================================================
// k_prep: g_w3kn[k][n] = rna_tf32(W_in[512+k][n])   (straight rounded copy)
__global__ void k_prep(const float* __restrict__ Win) {
    int k = blockIdx.x, n = threadIdx.x;
    g_w3kn[(size_t)k * 256 + n] = __uint_as_float(f2tf32(Win[(size_t)(512 + k) * 256 + n]));
}

// ===========================================================================
// s12: [1024,256] (nodes) @ W_in[0:512,:] -> g_s12 [1024,512] (fp32 exact)
__global__ void k_s12(const float* __restrict__ nodes, const float* __restrict__ Win,
                      const float* __restrict__ b_in) {
    __shared__ float As[16][64];
    __shared__ float Bs[16][64];
    int tid = threadIdx.x;
    int tx = tid & 15, ty = tid >> 4;
    int row0 = blockIdx.x * 64;
    int n0   = blockIdx.y * 64;
    float c[4][4] = {};
    for (int k0 = 0; k0 < 256; k0 += 16) {
        {
            int r = tid >> 2, kq = tid & 3;
            float4 v = *(const float4*)&nodes[(size_t)(row0 + r) * 256 + k0 + kq * 4];
            As[kq*4+0][r] = v.x; As[kq*4+1][r] = v.y; As[kq*4+2][r] = v.z; As[kq*4+3][r] = v.w;
        }
        {
            int k = tid >> 4, nq = tid & 15;
            int n = n0 + nq * 4;
            const float* src = (n < 256) ? &Win[(size_t)(k0 + k) * 256 + n]
                                         : &Win[(size_t)(256 + k0 + k) * 256 + (n - 256)];
            *(float4*)&Bs[k][nq*4] = *(const float4*)src;
        }
        __syncthreads();
#pragma unroll
        for (int k = 0; k < 16; k++) {
            float a[4], b[4];
            *(float4*)a = *(float4*)&As[k][ty*4];
            *(float4*)b = *(float4*)&Bs[k][tx*4];
#pragma unroll
            for (int i = 0; i < 4; i++)
#pragma unroll
                for (int j = 0; j < 4; j++) c[i][j] += a[i] * b[j];
        }
        __syncthreads();
    }
#pragma unroll
    for (int i = 0; i < 4; i++) {
        int row = row0 + ty*4 + i;
#pragma unroll
        for (int j = 0; j < 4; j++) {
            int n = n0 + tx*4 + j;
            float v = c[i][j] + (n >= 256 ? b_in[n - 256] : 0.f);
            g_s12[(size_t)row * 512 + n] = v;
        }
    }
}

// ===========================================================================
// k_main: mma.sync tf32 GEMM. cat = relu(edges @ W3 + s1 + s2); coef fused.
// CTA: BM=128 x BN=128 x BK=16, 256 thr (8 warps as 2M x 4N, warp 64x32).
#define ASTR 20    // As row stride (floats): conflict-free for frag loads
#define BSTR 132   // Bs row stride (floats)

__global__ void __launch_bounds__(256, 2) k_main(const float* __restrict__ edges,
                                                 const float* __restrict__ Wcoef,
                                                 float* __restrict__ cat) {
    __shared__ float As[2][128 * ASTR];
    __shared__ float Bs[2][16 * BSTR];
    __shared__ float s1s[128], wcs[128];
    __shared__ float red[128 * 4];

    int tid = threadIdx.x;
    int lane = tid & 31, wid = tid >> 5;
    int gid = lane >> 2, tig = lane & 3;
    int wm = wid & 1, wn = wid >> 1;          // warp grid 2 (M) x 4 (N)
    int m0w = wm * 64, n0w = wn * 32;

    int row0 = blockIdx.x * 128;
    int nblk = blockIdx.y;                    // 0 or 1 -> cols nblk*128..
    int bi = row0 >> 8;
    int b  = bi >> 8;

    s1s[tid & 127] = g_s12[(size_t)bi * 512 + nblk * 128 + (tid & 127)];
    wcs[tid & 127] = Wcoef[nblk * 128 + (tid & 127)];

    float acc[4][4][4] = {};                  // [mf][nf][reg]

    // ---- global->smem helpers
    const float* Aglob = &edges[(size_t)row0 * 256];
    const float* Bglob = &g_w3kn[(size_t)nblk * 128];

    int ar = (tid + 0) >> 2,  aq0 = (tid + 0) & 3;       // A: idx, idx+256
    int ar1 = (tid + 256) >> 2, aq1 = (tid + 256) & 3;
    int bk0 = tid >> 5, bq0 = tid & 31;                  // B: idx = tid, tid+256
    int bk1 = (tid + 256) >> 5, bq1 = (tid + 256) & 31;

    uint32_t bs_base0 = smem_u32(&Bs[0][0]);
    uint32_t bs_base1 = smem_u32(&Bs[1][0]);

    // ---- prologue: chunk 0
    {
        CP_ASYNC16(bs_base0 + (uint32_t)(bk0 * BSTR + bq0 * 4) * 4,
                   (const void*)&Bglob[(size_t)bk0 * 256 + bq0 * 4]);
        CP_ASYNC16(bs_base0 + (uint32_t)(bk1 * BSTR + bq1 * 4) * 4,
                   (const void*)&Bglob[(size_t)bk1 * 256 + bq1 * 4]);
        CP_COMMIT();
        float4 v0 = *(const float4*)&Aglob[(size_t)ar * 256 + aq0 * 4];
        float4 v1 = *(const float4*)&Aglob[(size_t)ar1 * 256 + aq1 * 4];
        uint4 t0 = { f2tf32(v0.x), f2tf32(v0.y), f2tf32(v0.z), f2tf32(v0.w) };
        uint4 t1 = { f2tf32(v1.x), f2tf32(v1.y), f2tf32(v1.z), f2tf32(v1.w) };
        *(uint4*)&As[0][ar * ASTR + aq0 * 4]  = t0;
        *(uint4*)&As[0][ar1 * ASTR + aq1 * 4] = t1;
        CP_WAIT0();
        __syncthreads();
    }

    for (int c = 0; c < 16; c++) {
        int s = c & 1, sn = s ^ 1;
        float4 v0, v1;
        if (c < 15) {
            int k0 = (c + 1) * 16;
            uint32_t bsb = sn ? bs_base1 : bs_base0;
            CP_ASYNC16(bsb + (uint32_t)(bk0 * BSTR + bq0 * 4) * 4,
                       (const void*)&Bglob[(size_t)(k0 + bk0) * 256 + bq0 * 4]);
            CP_ASYNC16(bsb + (uint32_t)(bk1 * BSTR + bq1 * 4) * 4,
                       (const void*)&Bglob[(size_t)(k0 + bk1) * 256 + bq1 * 4]);
            CP_COMMIT();
            v0 = *(const float4*)&Aglob[(size_t)ar * 256 + k0 + aq0 * 4];
            v1 = *(const float4*)&Aglob[(size_t)ar1 * 256 + k0 + aq1 * 4];
        }
        // ---- MMA over smem stage s
        const float* as = As[s];
        const float* bs = Bs[s];
#pragma unroll
        for (int ks = 0; ks < 2; ks++) {
            int kk = ks * 8;
            uint32_t a[4][4], bf[4][2];
#pragma unroll
            for (int mf = 0; mf < 4; mf++) {
                int mb = (m0w + mf * 16 + gid) * ASTR + kk + tig;
                a[mf][0] = __float_as_uint(as[mb]);
                a[mf][1] = __float_as_uint(as[mb + 8 * ASTR]);
                a[mf][2] = __float_as_uint(as[mb + 4]);
                a[mf][3] = __float_as_uint(as[mb + 8 * ASTR + 4]);
            }
#pragma unroll
            for (int nf = 0; nf < 4; nf++) {
                int nb = (kk + tig) * BSTR + n0w + nf * 8 + gid;
                bf[nf][0] = __float_as_uint(bs[nb]);
                bf[nf][1] = __float_as_uint(bs[nb + 4 * BSTR]);
            }
#pragma unroll
            for (int mf = 0; mf < 4; mf++)
#pragma unroll
                for (int nf = 0; nf < 4; nf++)
                    mma_tf32(acc[mf][nf], a[mf], bf[nf]);
        }
        if (c < 15) {
            uint4 t0 = { f2tf32(v0.x), f2tf32(v0.y), f2tf32(v0.z), f2tf32(v0.w) };
            uint4 t1 = { f2tf32(v1.x), f2tf32(v1.y), f2tf32(v1.z), f2tf32(v1.w) };
            *(uint4*)&As[sn][ar * ASTR + aq0 * 4]  = t0;
            *(uint4*)&As[sn][ar1 * ASTR + aq1 * 4] = t1;
        }
        CP_WAIT0();
        __syncthreads();
    }

    // ---- epilogue
#pragma unroll
    for (int mf = 0; mf < 4; mf++) {
#pragma unroll
        for (int rr = 0; rr < 2; rr++) {
            int row_local = m0w + mf * 16 + gid + rr * 8;
            int m  = row0 + row_local;
            int jj = (row0 & 255) + row_local;
            const float* s2p = &g_s12[((size_t)(b * 256 + jj)) * 512 + 256 + nblk * 128];
            float* catp = &cat[(size_t)m * 256 + nblk * 128];
            float csum = 0.f;
#pragma unroll
            for (int nf = 0; nf < 4; nf++) {
                int nl = n0w + nf * 8 + tig * 2;
                float v0 = acc[mf][nf][rr*2]   + s1s[nl]   + s2p[nl];
                float v1 = acc[mf][nf][rr*2+1] + s1s[nl+1] + s2p[nl+1];
                v0 = fmaxf(v0, 0.f); v1 = fmaxf(v1, 0.f);
                csum += v0 * wcs[nl] + v1 * wcs[nl + 1];
                float2 st = { v0, v1 };
                *(float2*)&catp[nl] = st;
            }
            csum += __shfl_xor_sync(0xffffffffu, csum, 1);
            csum += __shfl_xor_sync(0xffffffffu, csum, 2);
            if (tig == 0) red[row_local * 4 + wn] = csum;
        }
    }
    __syncthreads();
    if (tid < 128) {
        float s = red[tid*4] + red[tid*4+1] + red[tid*4+2] + red[tid*4+3];
        g_coef[(size_t)nblk * Mv + row0 + tid] = s;
    }
}

// ===========================================================================
// softmax over neighbors + weighted sum -> g_resid. block = (b,i), 256 threads
__global__ void k_softmax(const float* __restrict__ aux, const float* __restrict__ bcoef,
                          const float* __restrict__ cat) {
    __shared__ float attn[256];
    __shared__ float redbuf[8];
    int bi = blockIdx.x;
    int tid = threadIdx.x;
    size_t row = (size_t)bi * 256 + tid;
    float logit = aux[row] + g_coef[row] + g_coef[Mv + row] + bcoef[0];

    float v = logit;
#pragma unroll
    for (int o = 16; o > 0; o >>= 1) v = fmaxf(v, __shfl_xor_sync(0xffffffffu, v, o));
    if ((tid & 31) == 0) redbuf[tid >> 5] = v;
    __syncthreads();
    float mx = redbuf[0];
#pragma unroll
    for (int i = 1; i < 8; i++) mx = fmaxf(mx, redbuf[i]);

    float e = expf(logit - mx);
    v = e;
#pragma unroll
    for (int o = 16; o > 0; o >>= 1) v += __shfl_xor_sync(0xffffffffu, v, o);
    __syncthreads();
    if ((tid & 31) == 0) redbuf[tid >> 5] = v;
    __syncthreads();
    float s = 0.f;
#pragma unroll
    for (int i = 0; i < 8; i++) s += redbuf[i];
    attn[tid] = e / s;
    __syncthreads();

    const float* cp = &cat[(size_t)bi * 65536 + tid];
    float acc = 0.f;
#pragma unroll 8
    for (int j = 0; j < 256; j++) acc += attn[j] * cp[(size_t)j * 256];
    g_resid[row] = acc;
}

// ===========================================================================
// out: nodes + relu(resid @ W_out + b_out). BM=64 BN=64, grid (16,4)
__global__ void k_out(const float* __restrict__ nodes, const float* __restrict__ Wout,
                      const float* __restrict__ b_out, float* __restrict__ outn) {
    __shared__ float As[16][64];
    __shared__ float Bs[16][64];
    int tid = threadIdx.x;
    int tx = tid & 15, ty = tid >> 4;
    int row0 = blockIdx.x * 64;
    int n0   = blockIdx.y * 64;
    float c[4][4] = {};
    for (int k0 = 0; k0 < 256; k0 += 16) {
        {
            int r = tid >> 2, kq = tid & 3;
            float4 v = *(const float4*)&g_resid[(size_t)(row0 + r) * 256 + k0 + kq * 4];
            As[kq*4+0][r] = v.x; As[kq*4+1][r] = v.y; As[kq*4+2][r] = v.z; As[kq*4+3][r] = v.w;
        }
        {
            int k = tid >> 4, nq = tid & 15;
            *(float4*)&Bs[k][nq*4] = *(const float4*)&Wout[(size_t)(k0 + k) * 256 + n0 + nq * 4];
        }
        __syncthreads();
#pragma unroll
        for (int k = 0; k < 16; k++) {
            float a[4], b[4];
            *(float4*)a = *(float4*)&As[k][ty*4];
            *(float4*)b = *(float4*)&Bs[k][tx*4];
#pragma unroll
            for (int i = 0; i < 4; i++)
#pragma unroll
                for (int j = 0; j < 4; j++) c[i][j] += a[i] * b[j];
        }
        __syncthreads();
    }
#pragma unroll
    for (int i = 0; i < 4; i++) {
        int row = row0 + ty*4 + i;
#pragma unroll
        for (int j = 0; j < 4; j++) {
            int n = n0 + tx*4 + j;
            float v = fmaxf(c[i][j] + b_out[n], 0.f);
            outn[(size_t)row * 256 + n] = nodes[(size_t)row * 256 + n] + v;
        }
    }
}

// ===========================================================================
extern "C" void kernel_launch(void* const* d_in, const int* in_sizes, int n_in,
                              void* d_out, int out_size) {
    const float* nodes = (const float*)d_in[0];
    const float* edges = (const float*)d_in[1];
    const float* aux   = (const float*)d_in[2];
    // d_in[3] = nums (unused)
    const float* Win   = (const float*)d_in[4];
    const float* b_in  = (const float*)d_in[5];
    const float* Wcoef = (const float*)d_in[6];
    const float* bcoef = (const float*)d_in[7];
    const float* Wout  = (const float*)d_in[8];
    const float* b_out = (const float*)d_in[9];

    float* out_nodes = (float*)d_out;                    // [4,256,256]
    float* out_cat   = out_nodes + (size_t)BIv * Dv;     // [4,256,256,256]

    k_prep   <<<256, 256>>>(Win);
    k_s12    <<<dim3(16, 8), 256>>>(nodes, Win, b_in);
    k_main   <<<dim3(2048, 2), 256>>>(edges, Wcoef, out_cat);
    k_softmax<<<1024, 256>>>(aux, bcoef, out_cat);
    k_out    <<<dim3(16, 4), 256>>>(nodes, Wout, b_out, out_nodes);
}

// round 4
// speedup vs baseline: 2.1926x; 1.0483x over previous
#include <cuda_runtime.h>
#include <cstdint>

#define Bv 4
#define Nv 256
#define Dv 256
#define Mv (Bv*Nv*Nv)     // 262144 pair rows
#define BIv (Bv*Nv)       // 1024 (b,i) rows

// scratch (no allocations allowed)
__device__ __align__(16) float g_s12[BIv * 512];     // s1 (cols 0..255), s2+b_in (cols 256..511)
__device__ __align__(16) float g_coef[Mv];           // per-row coef logits (pre-bias)
__device__ __align__(16) float g_resid[BIv * Dv];
__device__ __align__(16) float g_w3kn[256 * 256];    // W_in[512:768,:], tf32-rounded, [k][n]

__device__ __forceinline__ uint32_t f2tf32(float x) {
    uint32_t u; asm("cvt.rna.tf32.f32 %0, %1;" : "=r"(u) : "f"(x)); return u;
}
__device__ __forceinline__ uint32_t smem_u32(const void* p) {
    uint32_t a;
    asm("{ .reg .u64 t; cvta.to.shared.u64 t, %1; cvt.u32.u64 %0, t; }" : "=r"(a) : "l"(p));
    return a;
}
__device__ __forceinline__ void mma_tf32(float* d, const uint32_t* a, const uint32_t* b) {
    asm volatile(
        "mma.sync.aligned.m16n8k8.row.col.f32.tf32.tf32.f32 "
        "{%0,%1,%2,%3}, {%4,%5,%6,%7}, {%8,%9}, {%0,%1,%2,%3};"
        : "+f"(d[0]), "+f"(d[1]), "+f"(d[2]), "+f"(d[3])
        : "r"(a[0]), "r"(a[1]), "r"(a[2]), "r"(a[3]), "r"(b[0]), "r"(b[1]));
}
#define CP_ASYNC16(s, g) \
    asm volatile("cp.async.ca.shared.global [%0], [%1], 16;" :: "r"(s), "l"(g))
#define CP_COMMIT()  asm volatile("cp.async.commit_group;" ::: "memory")
#define CP_WAIT0()   asm volatile("cp.async.wait_group 0;" ::: "memory")
#define CP_WAIT1()   asm volatile("cp.async.wait_group 1;" ::: "memory")

// ===========================================================================
// k_prep: g_w3kn[k][n] = rna_tf32(W_in[512+k][n])
__global__ void k_prep(const float* __restrict__ Win) {
    int k = blockIdx.x, n = threadIdx.x;
    g_w3kn[(size_t)k * 256 + n] = __uint_as_float(f2tf32(Win[(size_t)(512 + k) * 256 + n]));
}

// ===========================================================================
// s12: [1024,256] (nodes) @ W_in[0:512,:] -> g_s12 [1024,512] (fp32 exact)
__global__ void k_s12(const float* __restrict__ nodes, const float* __restrict__ Win,
                      const float* __restrict__ b_in) {
    __shared__ float As[16][64];
    __shared__ float Bs[16][64];
    int tid = threadIdx.x;
    int tx = tid & 15, ty = tid >> 4;
    int row0 = blockIdx.x * 64;
    int n0   = blockIdx.y * 64;
    float c[4][4] = {};
    for (int k0 = 0; k0 < 256; k0 += 16) {
        {
            int r = tid >> 2, kq = tid & 3;
            float4 v = *(const float4*)&nodes[(size_t)(row0 + r) * 256 + k0 + kq * 4];
            As[kq*4+0][r] = v.x; As[kq*4+1][r] = v.y; As[kq*4+2][r] = v.z; As[kq*4+3][r] = v.w;
        }
        {
            int k = tid >> 4, nq = tid & 15;
            int n = n0 + nq * 4;
            const float* src = (n < 256) ? &Win[(size_t)(k0 + k) * 256 + n]
                                         : &Win[(size_t)(256 + k0 + k) * 256 + (n - 256)];
            *(float4*)&Bs[k][nq*4] = *(const float4*)src;
        }
        __syncthreads();
#pragma unroll
        for (int k = 0; k < 16; k++) {
            float a[4], b[4];
            *(float4*)a = *(float4*)&As[k][ty*4];
            *(float4*)b = *(float4*)&Bs[k][tx*4];
#pragma unroll
            for (int i = 0; i < 4; i++)
#pragma unroll
                for (int j = 0; j < 4; j++) c[i][j] += a[i] * b[j];
        }
        __syncthreads();
    }
#pragma unroll
    for (int i = 0; i < 4; i++) {
        int row = row0 + ty*4 + i;
#pragma unroll
        for (int j = 0; j < 4; j++) {
            int n = n0 + tx*4 + j;
            float v = c[i][j] + (n >= 256 ? b_in[n - 256] : 0.f);
            g_s12[(size_t)row * 512 + n] = v;
        }
    }
}

// ===========================================================================
// k_main: mma.sync tf32. CTA: BM=128 x BN=256 x BK=16, 512 thr (4M x 4N warps,
// warp tile 32x64). 3-stage cp.async pipeline for A (raw fp32) and B (rounded).
#define ASTR 20    // As row stride (floats)
#define BSTR 264   // Bs row stride (floats)
#define OFF_A    0                       // 3 * 128*ASTR = 7680 f
#define OFF_B    7680                    // 3 * 16*BSTR  = 12672 f
#define OFF_S1   20352                   // 256 f
#define OFF_WC   20608                   // 256 f
#define OFF_RED  20864                   // 512 f
#define SMEM_MAIN_FLOATS 21376           // 85504 bytes

__global__ void __launch_bounds__(512, 1) k_main(const float* __restrict__ edges,
                                                 const float* __restrict__ Wcoef,
                                                 float* __restrict__ cat) {
    extern __shared__ __align__(16) float sm[];
    float* s1s = sm + OFF_S1;
    float* wcs = sm + OFF_WC;
    float* red = sm + OFF_RED;

    int tid = threadIdx.x;
    int lane = tid & 31, wid = tid >> 5;
    int gid = lane >> 2, tig = lane & 3;
    int wm = wid & 3, wn = wid >> 2;          // 4 (M) x 4 (N)
    int m0w = wm * 32, n0w = wn * 64;

    int row0 = blockIdx.x * 128;
    int bi = row0 >> 8;
    int b  = bi >> 8;

    if (tid < 256) {
        s1s[tid] = g_s12[(size_t)bi * 512 + tid];
        wcs[tid] = Wcoef[tid];
    }

    const float* Aglob = &edges[(size_t)row0 * 256];

    // cp.async source/dest mapping
    int am = tid >> 2, aq = tid & 3;               // A: 512 x 16B
    uint32_t a_dst = smem_u32(sm + OFF_A) + (uint32_t)(am * ASTR + aq * 4) * 4;
    const float* a_src = &Aglob[(size_t)am * 256 + aq * 4];
    int bidx0 = tid, bidx1 = tid + 512;            // B: 1024 x 16B
    int bk0 = bidx0 >> 6, bn0 = (bidx0 & 63) * 4;
    int bk1 = bidx1 >> 6, bn1 = (bidx1 & 63) * 4;
    uint32_t b_dst0 = smem_u32(sm + OFF_B) + (uint32_t)(bk0 * BSTR + bn0) * 4;
    uint32_t b_dst1 = smem_u32(sm + OFF_B) + (uint32_t)(bk1 * BSTR + bn1) * 4;

    const uint32_t A_STG = 128 * ASTR * 4;         // stage stride bytes
    const uint32_t B_STG = 16 * BSTR * 4;

    // prologue: chunks 0,1 into stages 0,1
#pragma unroll
    for (int c = 0; c < 2; c++) {
        int k0 = c * 16;
        CP_ASYNC16(a_dst + c * A_STG, (const void*)(a_src + k0));
        CP_ASYNC16(b_dst0 + c * B_STG, (const void*)&g_w3kn[(size_t)(k0 + bk0) * 256 + bn0]);
        CP_ASYNC16(b_dst1 + c * B_STG, (const void*)&g_w3kn[(size_t)(k0 + bk1) * 256 + bn1]);
        CP_COMMIT();
    }

    float acc[2][8][4] = {};                       // [mf][nf][reg]

    for (int c = 0; c < 16; c++) {
        int s = c - (c / 3) * 3;                   // c % 3
        CP_WAIT1();
        __syncthreads();
        // issue chunk c+2 into stage (c+2)%3
        if (c + 2 < 16) {
            int cn = c + 2;
            int sn = cn - (cn / 3) * 3;
            int k0 = cn * 16;
            CP_ASYNC16(a_dst + sn * A_STG, (const void*)(a_src + k0));
            CP_ASYNC16(b_dst0 + sn * B_STG, (const void*)&g_w3kn[(size_t)(k0 + bk0) * 256 + bn0]);
            CP_ASYNC16(b_dst1 + sn * B_STG, (const void*)&g_w3kn[(size_t)(k0 + bk1) * 256 + bn1]);
        }
        CP_COMMIT();                               // empty group when no issue keeps counts aligned

        const float* as = sm + OFF_A + s * (128 * ASTR);
        const float* bs = sm + OFF_B + s * (16 * BSTR);
#pragma unroll
        for (int ks = 0; ks < 2; ks++) {
            int kk = ks * 8;
            uint32_t a[2][4];
#pragma unroll
            for (int mf = 0; mf < 2; mf++) {
                int mb = (m0w + mf * 16 + gid) * ASTR + kk + tig;
                a[mf][0] = f2tf32(as[mb]);
                a[mf][1] = f2tf32(as[mb + 8 * ASTR]);
                a[mf][2] = f2tf32(as[mb + 4]);
                a[mf][3] = f2tf32(as[mb + 8 * ASTR + 4]);
            }
            uint32_t bf[8][2];
#pragma unroll
            for (int nf = 0; nf < 8; nf++) {
                int nb = (kk + tig) * BSTR + n0w + nf * 8 + gid;
                bf[nf][0] = __float_as_uint(bs[nb]);
                bf[nf][1] = __float_as_uint(bs[nb + 4 * BSTR]);
            }
#pragma unroll
            for (int mf = 0; mf < 2; mf++)
#pragma unroll
                for (int nf = 0; nf < 8; nf++)
                    mma_tf32(acc[mf][nf], a[mf], bf[nf]);
        }
    }

    // ---- epilogue
#pragma unroll
    for (int mf = 0; mf < 2; mf++) {
#pragma unroll
        for (int rr = 0; rr < 2; rr++) {
            int row_local = m0w + mf * 16 + gid + rr * 8;
            int m  = row0 + row_local;
            int jj = (row0 & 255) + row_local;
            const float* s2p = &g_s12[((size_t)(b * 256 + jj)) * 512 + 256];
            float* catp = &cat[(size_t)m * 256];
            float csum = 0.f;
#pragma unroll
            for (int nf = 0; nf < 8; nf++) {
                int nl = n0w + nf * 8 + tig * 2;
                float v0 = acc[mf][nf][rr*2]   + s1s[nl]   + s2p[nl];
                float v1 = acc[mf][nf][rr*2+1] + s1s[nl+1] + s2p[nl+1];
                v0 = fmaxf(v0, 0.f); v1 = fmaxf(v1, 0.f);
                csum += v0 * wcs[nl] + v1 * wcs[nl + 1];
                float2 st = { v0, v1 };
                *(float2*)&catp[nl] = st;
            }
            csum += __shfl_xor_sync(0xffffffffu, csum, 1);
            csum += __shfl_xor_sync(0xffffffffu, csum, 2);
            if (tig == 0) red[row_local * 4 + wn] = csum;
        }
    }
    __syncthreads();
    if (tid < 128) {
        float s = red[tid*4] + red[tid*4+1] + red[tid*4+2] + red[tid*4+3];
        g_coef[row0 + tid] = s;
    }
}

// ===========================================================================
// softmax over neighbors + weighted sum -> g_resid. block = (b,i), 256 threads
__global__ void k_softmax(const float* __restrict__ aux, const float* __restrict__ bcoef,
                          const float* __restrict__ cat) {
    __shared__ float attn[256];
    __shared__ float redbuf[8];
    int bi = blockIdx.x;
    int tid = threadIdx.x;
    size_t row = (size_t)bi * 256 + tid;
    float logit = aux[row] + g_coef[row] + bcoef[0];

    float v = logit;
#pragma unroll
    for (int o = 16; o > 0; o >>= 1) v = fmaxf(v, __shfl_xor_sync(0xffffffffu, v, o));
    if ((tid & 31) == 0) redbuf[tid >> 5] = v;
    __syncthreads();
    float mx = redbuf[0];
#pragma unroll
    for (int i = 1; i < 8; i++) mx = fmaxf(mx, redbuf[i]);

    float e = expf(logit - mx);
    v = e;
#pragma unroll
    for (int o = 16; o > 0; o >>= 1) v += __shfl_xor_sync(0xffffffffu, v, o);
    __syncthreads();
    if ((tid & 31) == 0) redbuf[tid >> 5] = v;
    __syncthreads();
    float s = 0.f;
#pragma unroll
    for (int i = 0; i < 8; i++) s += redbuf[i];
    attn[tid] = e / s;
    __syncthreads();

    const float* cp = &cat[(size_t)bi * 65536 + tid];
    float acc = 0.f;
#pragma unroll 8
    for (int j = 0; j < 256; j++) acc += attn[j] * cp[(size_t)j * 256];
    g_resid[row] = acc;
}

// ===========================================================================
// out: nodes + relu(resid @ W_out + b_out). BM=64 BN=64, grid (16,4)
__global__ void k_out(const float* __restrict__ nodes, const float* __restrict__ Wout,
                      const float* __restrict__ b_out, float* __restrict__ outn) {
    __shared__ float As[16][64];
    __shared__ float Bs[16][64];
    int tid = threadIdx.x;
    int tx = tid & 15, ty = tid >> 4;
    int row0 = blockIdx.x * 64;
    int n0   = blockIdx.y * 64;
    float c[4][4] = {};
    for (int k0 = 0; k0 < 256; k0 += 16) {
        {
            int r = tid >> 2, kq = tid & 3;
            float4 v = *(const float4*)&g_resid[(size_t)(row0 + r) * 256 + k0 + kq * 4];
            As[kq*4+0][r] = v.x; As[kq*4+1][r] = v.y; As[kq*4+2][r] = v.z; As[kq*4+3][r] = v.w;
        }
        {
            int k = tid >> 4, nq = tid & 15;
            *(float4*)&Bs[k][nq*4] = *(const float4*)&Wout[(size_t)(k0 + k) * 256 + n0 + nq * 4];
        }
        __syncthreads();
#pragma unroll
        for (int k = 0; k < 16; k++) {
            float a[4], b[4];
            *(float4*)a = *(float4*)&As[k][ty*4];
            *(float4*)b = *(float4*)&Bs[k][tx*4];
#pragma unroll
            for (int i = 0; i < 4; i++)
#pragma unroll
                for (int j = 0; j < 4; j++) c[i][j] += a[i] * b[j];
        }
        __syncthreads();
    }
#pragma unroll
    for (int i = 0; i < 4; i++) {
        int row = row0 + ty*4 + i;
#pragma unroll
        for (int j = 0; j < 4; j++) {
            int n = n0 + tx*4 + j;
            float v = fmaxf(c[i][j] + b_out[n], 0.f);
            outn[(size_t)row * 256 + n] = nodes[(size_t)row * 256 + n] + v;
        }
    }
}

// ===========================================================================
extern "C" void kernel_launch(void* const* d_in, const int* in_sizes, int n_in,
                              void* d_out, int out_size) {
    const float* nodes = (const float*)d_in[0];
    const float* edges = (const float*)d_in[1];
    const float* aux   = (const float*)d_in[2];
    // d_in[3] = nums (unused)
    const float* Win   = (const float*)d_in[4];
    const float* b_in  = (const float*)d_in[5];
    const float* Wcoef = (const float*)d_in[6];
    const float* bcoef = (const float*)d_in[7];
    const float* Wout  = (const float*)d_in[8];
    const float* b_out = (const float*)d_in[9];

    float* out_nodes = (float*)d_out;                    // [4,256,256]
    float* out_cat   = out_nodes + (size_t)BIv * Dv;     // [4,256,256,256]

    cudaFuncSetAttribute(k_main, cudaFuncAttributeMaxDynamicSharedMemorySize,
                         SMEM_MAIN_FLOATS * 4);

    k_prep   <<<256, 256>>>(Win);
    k_s12    <<<dim3(16, 8), 256>>>(nodes, Win, b_in);
    k_main   <<<2048, 512, SMEM_MAIN_FLOATS * 4>>>(edges, Wcoef, out_cat);
    k_softmax<<<1024, 256>>>(aux, bcoef, out_cat);
    k_out    <<<dim3(16, 4), 256>>>(nodes, Wout, b_out, out_nodes);
}

// round 5
// speedup vs baseline: 2.3420x; 1.0681x over previous
#include <cuda_runtime.h>
#include <cstdint>

#define Bv 4
#define Nv 256
#define Dv 256
#define Mv (Bv*Nv*Nv)     // 262144 pair rows
#define BIv (Bv*Nv)       // 1024 (b,i) rows

// scratch (no allocations allowed)
__device__ __align__(16) float g_s12[BIv * 512];     // s1 (cols 0..255), s2+b_in (cols 256..511)
__device__ __align__(16) float g_coef[Mv];           // per-row coef logits (pre-bias)
__device__ __align__(16) float g_resid[BIv * Dv];
// W_in[512:768,:] tf32-rounded, permuted: [kg][n][8], inner k order {0,4,1,5,2,6,3,7}
__device__ __align__(16) float g_w3p[256 * 256];

__device__ __forceinline__ uint32_t f2tf32(float x) {
    uint32_t u; asm("cvt.rna.tf32.f32 %0, %1;" : "=r"(u) : "f"(x)); return u;
}
__device__ __forceinline__ uint32_t smem_u32(const void* p) {
    uint32_t a;
    asm("{ .reg .u64 t; cvta.to.shared.u64 t, %1; cvt.u32.u64 %0, t; }" : "=r"(a) : "l"(p));
    return a;
}
__device__ __forceinline__ void mma_tf32(float* d, const uint32_t* a, const uint32_t* b) {
    asm volatile(
        "mma.sync.aligned.m16n8k8.row.col.f32.tf32.tf32.f32 "
        "{%0,%1,%2,%3}, {%4,%5,%6,%7}, {%8,%9}, {%0,%1,%2,%3};"
        : "+f"(d[0]), "+f"(d[1]), "+f"(d[2]), "+f"(d[3])
        : "r"(a[0]), "r"(a[1]), "r"(a[2]), "r"(a[3]), "r"(b[0]), "r"(b[1]));
}
#define CP_ASYNC16(s, g) \
    asm volatile("cp.async.ca.shared.global [%0], [%1], 16;" :: "r"(s), "l"(g))
#define CP_COMMIT()  asm volatile("cp.async.commit_group;" ::: "memory")
#define CP_WAIT1()   asm volatile("cp.async.wait_group 1;" ::: "memory")

// ===========================================================================
// k_prep: permuted tf32 copy of W_in[512:768,:]
__global__ void k_prep(const float* __restrict__ Win) {
    int k = blockIdx.x, n = threadIdx.x;
    int kg = k >> 3, r = k & 7;
    int p = (r < 4) ? (2 * r) : (2 * (r - 4) + 1);
    g_w3p[((size_t)kg * 256 + n) * 8 + p] =
        __uint_as_float(f2tf32(Win[(size_t)(512 + k) * 256 + n]));
}

// ===========================================================================
// s12: [1024,256] (nodes) @ W_in[0:512,:] -> g_s12 [1024,512] (fp32 exact)
__global__ void k_s12(const float* __restrict__ nodes, const float* __restrict__ Win,
                      const float* __restrict__ b_in) {
    __shared__ float As[16][64];
    __shared__ float Bs[16][64];
    int tid = threadIdx.x;
    int tx = tid & 15, ty = tid >> 4;
    int row0 = blockIdx.x * 64;
    int n0   = blockIdx.y * 64;
    float c[4][4] = {};
    for (int k0 = 0; k0 < 256; k0 += 16) {
        {
            int r = tid >> 2, kq = tid & 3;
            float4 v = *(const float4*)&nodes[(size_t)(row0 + r) * 256 + k0 + kq * 4];
            As[kq*4+0][r] = v.x; As[kq*4+1][r] = v.y; As[kq*4+2][r] = v.z; As[kq*4+3][r] = v.w;
        }
        {
            int k = tid >> 4, nq = tid & 15;
            int n = n0 + nq * 4;
            const float* src = (n < 256) ? &Win[(size_t)(k0 + k) * 256 + n]
                                         : &Win[(size_t)(256 + k0 + k) * 256 + (n - 256)];
            *(float4*)&Bs[k][nq*4] = *(const float4*)src;
        }
        __syncthreads();
#pragma unroll
        for (int k = 0; k < 16; k++) {
            float a[4], b[4];
            *(float4*)a = *(float4*)&As[k][ty*4];
            *(float4*)b = *(float4*)&Bs[k][tx*4];
#pragma unroll
            for (int i = 0; i < 4; i++)
#pragma unroll
                for (int j = 0; j < 4; j++) c[i][j] += a[i] * b[j];
        }
        __syncthreads();
    }
#pragma unroll
    for (int i = 0; i < 4; i++) {
        int row = row0 + ty*4 + i;
#pragma unroll
        for (int j = 0; j < 4; j++) {
            int n = n0 + tx*4 + j;
            float v = c[i][j] + (n >= 256 ? b_in[n - 256] : 0.f);
            g_s12[(size_t)row * 512 + n] = v;
        }
    }
}

// ===========================================================================
// k_main: mma.sync tf32. CTA: BM=64 x BN=256 x BK=16, 256 thr (2M x 4N warps,
// warp tile 32x64). 3-stage cp.async. B fragments via LDS.64 (permuted layout).
#define ASTR 20                          // As row stride (floats)
#define A_STG_F (64 * ASTR)              // 1280 floats per stage
#define B_STG_F 4096                     // 16 x 256 packed floats per stage
#define OFF_A   0                        // 3 stages: 3840 f
#define OFF_B   3840                     // 3 stages: 12288 f
#define OFF_S1  16128                    // 256 f
#define OFF_WC  16384                    // 256 f
#define OFF_RED 16640                    // 256 f
#define SMEM_MAIN_FLOATS 16896           // 67584 bytes

__global__ void __launch_bounds__(256, 2) k_main(const float* __restrict__ edges,
                                                 const float* __restrict__ Wcoef,
                                                 float* __restrict__ cat) {
    extern __shared__ __align__(16) float sm[];
    float* s1s = sm + OFF_S1;
    float* wcs = sm + OFF_WC;
    float* red = sm + OFF_RED;

    int tid = threadIdx.x;
    int lane = tid & 31, wid = tid >> 5;
    int gid = lane >> 2, tig = lane & 3;
    int wm = wid & 1, wn = wid >> 1;          // 2 (M) x 4 (N)
    int m0w = wm * 32, n0w = wn * 64;

    int row0 = blockIdx.x * 64;               // 64 pair-rows, same (b,i)
    int bi = row0 >> 8;
    int b  = bi >> 8;

    s1s[tid] = g_s12[(size_t)bi * 512 + tid];
    wcs[tid] = Wcoef[tid];

    // ---- cp.async mappings
    int am = tid >> 2, aq = tid & 3;          // A: 256 x 16B chunks
    uint32_t a_dst = smem_u32(sm + OFF_A) + (uint32_t)(am * ASTR + aq * 4) * 4;
    const float* a_src = &edges[(size_t)(row0 + am) * 256 + aq * 4];
    uint32_t b_dst = smem_u32(sm + OFF_B) + (uint32_t)tid * 16;
    const float* b_base = g_w3p;              // chunk c -> offset c*4096 floats

    // prologue: chunks 0,1
#pragma unroll
    for (int c = 0; c < 2; c++) {
        CP_ASYNC16(a_dst + c * (A_STG_F * 4), (const void*)(a_src + c * 16));
#pragma unroll
        for (int i = 0; i < 4; i++)
            CP_ASYNC16(b_dst + c * (B_STG_F * 4) + i * 4096,
                       (const void*)(b_base + (size_t)c * B_STG_F + (tid + i * 256) * 4));
        CP_COMMIT();
    }

    float acc[2][8][4] = {};                  // [mf][nf][reg]

    for (int c = 0; c < 16; c++) {
        int s = c - (c / 3) * 3;
        CP_WAIT1();
        __syncthreads();
        if (c + 2 < 16) {
            int cn = c + 2;
            int sn = cn - (cn / 3) * 3;
            CP_ASYNC16(a_dst + sn * (A_STG_F * 4), (const void*)(a_src + cn * 16));
#pragma unroll
            for (int i = 0; i < 4; i++)
                CP_ASYNC16(b_dst + sn * (B_STG_F * 4) + i * 4096,
                           (const void*)(b_base + (size_t)cn * B_STG_F + (tid + i * 256) * 4));
        }
        CP_COMMIT();

        const float* as = sm + OFF_A + s * A_STG_F;
        const float* bs = sm + OFF_B + s * B_STG_F;
#pragma unroll
        for (int ks = 0; ks < 2; ks++) {
            int kk = ks * 8;
            uint32_t a[2][4];
#pragma unroll
            for (int mf = 0; mf < 2; mf++) {
                int mb = (m0w + mf * 16 + gid) * ASTR + kk + tig;
                a[mf][0] = f2tf32(as[mb]);
                a[mf][1] = f2tf32(as[mb + 8 * ASTR]);
                a[mf][2] = f2tf32(as[mb + 4]);
                a[mf][3] = f2tf32(as[mb + 8 * ASTR + 4]);
            }
            uint32_t bf[8][2];
#pragma unroll
            for (int nf = 0; nf < 8; nf++) {
                int n = n0w + nf * 8 + gid;
                float2 pv = *(const float2*)&bs[ks * 2048 + n * 8 + tig * 2];
                bf[nf][0] = __float_as_uint(pv.x);
                bf[nf][1] = __float_as_uint(pv.y);
            }
#pragma unroll
            for (int mf = 0; mf < 2; mf++)
#pragma unroll
                for (int nf = 0; nf < 8; nf++)
                    mma_tf32(acc[mf][nf], a[mf], bf[nf]);
        }
    }

    // ---- epilogue
#pragma unroll
    for (int mf = 0; mf < 2; mf++) {
#pragma unroll
        for (int rr = 0; rr < 2; rr++) {
            int row_local = m0w + mf * 16 + gid + rr * 8;
            int m  = row0 + row_local;
            int jj = (row0 & 255) + row_local;
            const float* s2p = &g_s12[((size_t)(b * 256 + jj)) * 512 + 256];
            float* catp = &cat[(size_t)m * 256];
            float csum = 0.f;
#pragma unroll
            for (int nf = 0; nf < 8; nf++) {
                int nl = n0w + nf * 8 + tig * 2;
                float v0 = acc[mf][nf][rr*2]   + s1s[nl]   + s2p[nl];
                float v1 = acc[mf][nf][rr*2+1] + s1s[nl+1] + s2p[nl+1];
                v0 = fmaxf(v0, 0.f); v1 = fmaxf(v1, 0.f);
                csum += v0 * wcs[nl] + v1 * wcs[nl + 1];
                float2 st = { v0, v1 };
                *(float2*)&catp[nl] = st;
            }
            csum += __shfl_xor_sync(0xffffffffu, csum, 1);
            csum += __shfl_xor_sync(0xffffffffu, csum, 2);
            if (tig == 0) red[row_local * 4 + wn] = csum;
        }
    }
    __syncthreads();
    if (tid < 64) {
        float s = red[tid*4] + red[tid*4+1] + red[tid*4+2] + red[tid*4+3];
        g_coef[row0 + tid] = s;
    }
}

// ===========================================================================
// softmax over neighbors + weighted sum -> g_resid. block = (b,i), 256 threads
__global__ void k_softmax(const float* __restrict__ aux, const float* __restrict__ bcoef,
                          const float* __restrict__ cat) {
    __shared__ float attn[256];
    __shared__ float redbuf[8];
    int bi = blockIdx.x;
    int tid = threadIdx.x;
    size_t row = (size_t)bi * 256 + tid;
    float logit = aux[row] + g_coef[row] + bcoef[0];

    float v = logit;
#pragma unroll
    for (int o = 16; o > 0; o >>= 1) v = fmaxf(v, __shfl_xor_sync(0xffffffffu, v, o));
    if ((tid & 31) == 0) redbuf[tid >> 5] = v;
    __syncthreads();
    float mx = redbuf[0];
#pragma unroll
    for (int i = 1; i < 8; i++) mx = fmaxf(mx, redbuf[i]);

    float e = expf(logit - mx);
    v = e;
#pragma unroll
    for (int o = 16; o > 0; o >>= 1) v += __shfl_xor_sync(0xffffffffu, v, o);
    __syncthreads();
    if ((tid & 31) == 0) redbuf[tid >> 5] = v;
    __syncthreads();
    float s = 0.f;
#pragma unroll
    for (int i = 0; i < 8; i++) s += redbuf[i];
    attn[tid] = e / s;
    __syncthreads();

    const float* cp = &cat[(size_t)bi * 65536 + tid];
    float acc = 0.f;
#pragma unroll 8
    for (int j = 0; j < 256; j++) acc += attn[j] * cp[(size_t)j * 256];
    g_resid[row] = acc;
}

// ===========================================================================
// out: nodes + relu(resid @ W_out + b_out). BM=32 BN=64, grid (32,4)
__global__ void k_out(const float* __restrict__ nodes, const float* __restrict__ Wout,
                      const float* __restrict__ b_out, float* __restrict__ outn) {
    __shared__ float As[16][32];
    __shared__ float Bs[16][64];
    int tid = threadIdx.x;
    int tx = tid & 15, ty = tid >> 4;      // tx: 16 col groups of 4; ty: 16 row groups of 2
    int row0 = blockIdx.x * 32;
    int n0   = blockIdx.y * 64;
    float c[2][4] = {};
    for (int k0 = 0; k0 < 256; k0 += 16) {
        {
            int f = tid;                    // 128 chunks of 16B: 32 rows x 4 quads
            if (f < 128) {
                int r = f >> 2, kq = f & 3;
                float4 v = *(const float4*)&g_resid[(size_t)(row0 + r) * 256 + k0 + kq * 4];
                As[kq*4+0][r] = v.x; As[kq*4+1][r] = v.y; As[kq*4+2][r] = v.z; As[kq*4+3][r] = v.w;
            }
        }
        {
            int k = tid >> 4, nq = tid & 15;
            *(float4*)&Bs[k][nq*4] = *(const float4*)&Wout[(size_t)(k0 + k) * 256 + n0 + nq * 4];
        }
        __syncthreads();
#pragma unroll
        for (int k = 0; k < 16; k++) {
            float a0 = As[k][ty*2], a1 = As[k][ty*2+1];
            float bb[4];
            *(float4*)bb = *(float4*)&Bs[k][tx*4];
#pragma unroll
            for (int j = 0; j < 4; j++) { c[0][j] += a0 * bb[j]; c[1][j] += a1 * bb[j]; }
        }
        __syncthreads();
    }
#pragma unroll
    for (int i = 0; i < 2; i++) {
        int row = row0 + ty*2 + i;
#pragma unroll
        for (int j = 0; j < 4; j++) {
            int n = n0 + tx*4 + j;
            float v = fmaxf(c[i][j] + b_out[n], 0.f);
            outn[(size_t)row * 256 + n] = nodes[(size_t)row * 256 + n] + v;
        }
    }
}

// ===========================================================================
extern "C" void kernel_launch(void* const* d_in, const int* in_sizes, int n_in,
                              void* d_out, int out_size) {
    const float* nodes = (const float*)d_in[0];
    const float* edges = (const float*)d_in[1];
    const float* aux   = (const float*)d_in[2];
    // d_in[3] = nums (unused)
    const float* Win   = (const float*)d_in[4];
    const float* b_in  = (const float*)d_in[5];
    const float* Wcoef = (const float*)d_in[6];
    const float* bcoef = (const float*)d_in[7];
    const float* Wout  = (const float*)d_in[8];
    const float* b_out = (const float*)d_in[9];

    float* out_nodes = (float*)d_out;                    // [4,256,256]
    float* out_cat   = out_nodes + (size_t)BIv * Dv;     // [4,256,256,256]

    cudaFuncSetAttribute(k_main, cudaFuncAttributeMaxDynamicSharedMemorySize,
                         SMEM_MAIN_FLOATS * 4);

    k_prep   <<<256, 256>>>(Win);
    k_s12    <<<dim3(16, 8), 256>>>(nodes, Win, b_in);
    k_main   <<<4096, 256, SMEM_MAIN_FLOATS * 4>>>(edges, Wcoef, out_cat);
    k_softmax<<<1024, 256>>>(aux, bcoef, out_cat);
    k_out    <<<dim3(32, 4), 256>>>(nodes, Wout, b_out, out_nodes);
}

// round 6
// speedup vs baseline: 3.0029x; 1.2822x over previous
#include <cuda_runtime.h>
#include <cuda_fp16.h>
#include <cstdint>
#include <cstring>

#define Bv 4
#define Nv 256
#define Dv 256
#define Mv (Bv*Nv*Nv)     // 262144 pair rows
#define BIv (Bv*Nv)       // 1024 (b,i) rows

// scratch (no allocations allowed)
__device__ __align__(16) float g_s12[BIv * 512];     // s1 (cols 0..255), s2+b_in (cols 256..511)
__device__ __align__(16) float g_coef[Mv];           // per-row coef logits (pre-bias)
__device__ __align__(16) float g_resid[BIv * Dv];
// W_in[512:768,:] fp16, layout [c32][kg16][n][16perm]; perm: thread tig gets k {2t,2t+1,2t+8,2t+9}
__device__ __align__(16) __half g_w3h[256 * 256];

__device__ __forceinline__ uint32_t smem_u32(const void* p) {
    uint32_t a;
    asm("{ .reg .u64 t; cvta.to.shared.u64 t, %1; cvt.u32.u64 %0, t; }" : "=r"(a) : "l"(p));
    return a;
}
__device__ __forceinline__ uint32_t f2h2(float a, float b) {
    __half2 h = __floats2half2_rn(a, b);
    uint32_t u; memcpy(&u, &h, 4); return u;
}
__device__ __forceinline__ void mma_f16(float* d, const uint32_t* a, const uint32_t* b) {
    asm volatile(
        "mma.sync.aligned.m16n8k16.row.col.f32.f16.f16.f32 "
        "{%0,%1,%2,%3}, {%4,%5,%6,%7}, {%8,%9}, {%0,%1,%2,%3};"
        : "+f"(d[0]), "+f"(d[1]), "+f"(d[2]), "+f"(d[3])
        : "r"(a[0]), "r"(a[1]), "r"(a[2]), "r"(a[3]), "r"(b[0]), "r"(b[1]));
}
__device__ __forceinline__ void ldsm4(uint32_t* r, uint32_t addr) {
    asm volatile("ldmatrix.sync.aligned.m8n8.x4.shared.b16 {%0,%1,%2,%3}, [%4];"
        : "=r"(r[0]), "=r"(r[1]), "=r"(r[2]), "=r"(r[3]) : "r"(addr));
}
#define CP_ASYNC16(s, g) \
    asm volatile("cp.async.ca.shared.global [%0], [%1], 16;" :: "r"(s), "l"(g))
#define CP_COMMIT()  asm volatile("cp.async.commit_group;" ::: "memory")
#define CP_WAIT1()   asm volatile("cp.async.wait_group 1;" ::: "memory")

// ===========================================================================
// k_prep: fp16 permuted copy of W_in[512:768,:]
__global__ void k_prep(const float* __restrict__ Win) {
    int k = blockIdx.x, n = threadIdx.x;
    int c = k >> 5, kg = (k >> 4) & 1, kk = k & 15;
    int t = (kk & 7) >> 1;
    int u = (kk & 1) + ((kk >> 3) << 1);
    int p = t * 4 + u;
    g_w3h[(((size_t)(c * 2 + kg)) * 256 + n) * 16 + p] =
        __float2half_rn(Win[(size_t)(512 + k) * 256 + n]);
}

// ===========================================================================
// s12: [1024,256] (nodes) @ W_in[0:512,:] -> g_s12 [1024,512] (fp32 exact)
__global__ void k_s12(const float* __restrict__ nodes, const float* __restrict__ Win,
                      const float* __restrict__ b_in) {
    __shared__ float As[16][64];
    __shared__ float Bs[16][64];
    int tid = threadIdx.x;
    int tx = tid & 15, ty = tid >> 4;
    int row0 = blockIdx.x * 64;
    int n0   = blockIdx.y * 64;
    float c[4][4] = {};
    for (int k0 = 0; k0 < 256; k0 += 16) {
        {
            int r = tid >> 2, kq = tid & 3;
            float4 v = *(const float4*)&nodes[(size_t)(row0 + r) * 256 + k0 + kq * 4];
            As[kq*4+0][r] = v.x; As[kq*4+1][r] = v.y; As[kq*4+2][r] = v.z; As[kq*4+3][r] = v.w;
        }
        {
            int k = tid >> 4, nq = tid & 15;
            int n = n0 + nq * 4;
            const float* src = (n < 256) ? &Win[(size_t)(k0 + k) * 256 + n]
                                         : &Win[(size_t)(256 + k0 + k) * 256 + (n - 256)];
            *(float4*)&Bs[k][nq*4] = *(const float4*)src;
        }
        __syncthreads();
#pragma unroll
        for (int k = 0; k < 16; k++) {
            float a[4], b[4];
            *(float4*)a = *(float4*)&As[k][ty*4];
            *(float4*)b = *(float4*)&Bs[k][tx*4];
#pragma unroll
            for (int i = 0; i < 4; i++)
#pragma unroll
                for (int j = 0; j < 4; j++) c[i][j] += a[i] * b[j];
        }
        __syncthreads();
    }
#pragma unroll
    for (int i = 0; i < 4; i++) {
        int row = row0 + ty*4 + i;
#pragma unroll
        for (int j = 0; j < 4; j++) {
            int n = n0 + tx*4 + j;
            float v = c[i][j] + (n >= 256 ? b_in[n - 256] : 0.f);
            g_s12[(size_t)row * 512 + n] = v;
        }
    }
}

// ===========================================================================
// k_main: fp16 mma m16n8k16. CTA: BM=64 x BN=256 x BK=32, 256 thr
// (2M x 4N warps, warp tile 32x64). A: LDG->cvt->STS 2-stage (ldmatrix frags);
// B: cp.async 3-stage fp16 pre-permuted (LDS.64 frags). 8 chunks, 8 syncs.
#define A_STG_B 5120                     // 64 rows x 80B (40 halves padded)
#define B_STG_B 16384                    // 32k x 256n x 2B
#define OFF_A   0                        // 2 stages: 10240
#define OFF_B   10240                    // 3 stages: 49152
#define OFF_S1  59392
#define OFF_WC  60416
#define OFF_RED 61440
#define SMEM_MAIN_BYTES 62464

__global__ void __launch_bounds__(256, 2) k_main(const float* __restrict__ edges,
                                                 const float* __restrict__ Wcoef,
                                                 float* __restrict__ cat) {
    extern __shared__ __align__(128) char smc[];
    float* s1s = (float*)(smc + OFF_S1);
    float* wcs = (float*)(smc + OFF_WC);
    float* red = (float*)(smc + OFF_RED);

    int tid = threadIdx.x;
    int lane = tid & 31, wid = tid >> 5;
    int gid = lane >> 2, tig = lane & 3;
    int wm = wid & 1, wn = wid >> 1;          // 2 (M) x 4 (N)
    int m0w = wm * 32, n0w = wn * 64;

    int row0 = blockIdx.x * 64;
    int bi = row0 >> 8;
    int b  = bi >> 8;

    s1s[tid] = g_s12[(size_t)bi * 512 + tid];
    wcs[tid] = Wcoef[tid];

    // A mappings: thread -> row r, 8-float segment j
    int ar = tid >> 2, aj = tid & 3;
    const float* a_src = &edges[(size_t)(row0 + ar) * 256 + aj * 8];
    uint32_t a_sts = smem_u32(smc + OFF_A) + (uint32_t)(ar * 80 + aj * 16);

    // B cp mappings
    uint32_t b_smem = smem_u32(smc + OFF_B);
    const char* b_gbase = (const char*)g_w3h;

    float4 rb[2][2];

    // ldmatrix lane addressing
    int lrow = ((lane >> 3) & 1) * 8 + (lane & 7);
    int lkb  = (lane >> 4) * 16;

#define LDGA(c, bf) do { \
        rb[bf][0] = *(const float4*)(a_src + (c) * 32); \
        rb[bf][1] = *(const float4*)(a_src + (c) * 32 + 4); } while (0)
#define STSA(c, bf) do { \
        uint4 t_; \
        t_.x = f2h2(rb[bf][0].x, rb[bf][0].y); \
        t_.y = f2h2(rb[bf][0].z, rb[bf][0].w); \
        t_.z = f2h2(rb[bf][1].x, rb[bf][1].y); \
        t_.w = f2h2(rb[bf][1].z, rb[bf][1].w); \
        asm volatile("st.shared.v4.b32 [%0], {%1,%2,%3,%4};" \
            :: "r"(a_sts + ((c) & 1) * A_STG_B), "r"(t_.x), "r"(t_.y), "r"(t_.z), "r"(t_.w) \
            : "memory"); } while (0)
#define CPB(c) do { \
        int s3_ = (c) - ((c) / 3) * 3; \
        _Pragma("unroll") \
        for (int i_ = 0; i_ < 4; i_++) { \
            int u_ = tid + i_ * 256; \
            int kg_ = u_ >> 9, n_ = (u_ >> 1) & 255, h_ = u_ & 1; \
            uint32_t d_ = b_smem + s3_ * B_STG_B + kg_ * 8192 + n_ * 32 + h_ * 16; \
            const void* s_ = b_gbase + (((size_t)((c) * 2 + kg_)) * 256 + n_) * 32 + h_ * 16; \
            CP_ASYNC16(d_, s_); \
        } } while (0)

    // ---- prologue
    LDGA(0, 0); LDGA(1, 1);
    CPB(0); CP_COMMIT();
    CPB(1); CP_COMMIT();
    STSA(0, 0);
    CP_WAIT1();
    __syncthreads();

    float acc[2][8][4] = {};

#pragma unroll
    for (int c = 0; c < 8; c++) {
        if (c + 2 < 8) CPB(c + 2);
        CP_COMMIT();
        if (c + 1 < 8) STSA(c + 1, (c + 1) & 1);
        if (c + 2 < 8) LDGA(c + 2, c & 1);

        uint32_t aBase = smem_u32(smc + OFF_A) + (c & 1) * A_STG_B;
        const char* Bs_ = smc + OFF_B + (c - (c / 3) * 3) * B_STG_B;
#pragma unroll
        for (int ks = 0; ks < 2; ks++) {
            uint32_t a[2][4];
#pragma unroll
            for (int mf = 0; mf < 2; mf++)
                ldsm4(a[mf], aBase + (uint32_t)((m0w + mf * 16 + lrow) * 80 + ks * 32 + lkb));
            uint32_t bf[8][2];
#pragma unroll
            for (int nf = 0; nf < 8; nf++) {
                int n = n0w + nf * 8 + gid;
                uint2 pv = *(const uint2*)(Bs_ + ks * 8192 + n * 32 + tig * 8);
                bf[nf][0] = pv.x; bf[nf][1] = pv.y;
            }
#pragma unroll
            for (int mf = 0; mf < 2; mf++)
#pragma unroll
                for (int nf = 0; nf < 8; nf++)
                    mma_f16(acc[mf][nf], a[mf], bf[nf]);
        }
        CP_WAIT1();
        __syncthreads();
    }

    // ---- epilogue
#pragma unroll
    for (int mf = 0; mf < 2; mf++) {
#pragma unroll
        for (int rr = 0; rr < 2; rr++) {
            int row_local = m0w + mf * 16 + gid + rr * 8;
            int m  = row0 + row_local;
            int jj = (row0 & 255) + row_local;
            const float* s2p = &g_s12[((size_t)(b * 256 + jj)) * 512 + 256];
            float* catp = &cat[(size_t)m * 256];
            float csum = 0.f;
#pragma unroll
            for (int nf = 0; nf < 8; nf++) {
                int nl = n0w + nf * 8 + tig * 2;
                float v0 = acc[mf][nf][rr*2]   + s1s[nl]   + s2p[nl];
                float v1 = acc[mf][nf][rr*2+1] + s1s[nl+1] + s2p[nl+1];
                v0 = fmaxf(v0, 0.f); v1 = fmaxf(v1, 0.f);
                csum += v0 * wcs[nl] + v1 * wcs[nl + 1];
                float2 st = { v0, v1 };
                *(float2*)&catp[nl] = st;
            }
            csum += __shfl_xor_sync(0xffffffffu, csum, 1);
            csum += __shfl_xor_sync(0xffffffffu, csum, 2);
            if (tig == 0) red[row_local * 4 + wn] = csum;
        }
    }
    __syncthreads();
    if (tid < 64) {
        float s = red[tid*4] + red[tid*4+1] + red[tid*4+2] + red[tid*4+3];
        g_coef[row0 + tid] = s;
    }
}

// ===========================================================================
// softmax over neighbors + weighted sum -> g_resid. block = (b,i), 256 threads
__global__ void k_softmax(const float* __restrict__ aux, const float* __restrict__ bcoef,
                          const float* __restrict__ cat) {
    __shared__ float attn[256];
    __shared__ float redbuf[8];
    int bi = blockIdx.x;
    int tid = threadIdx.x;
    size_t row = (size_t)bi * 256 + tid;
    float logit = aux[row] + g_coef[row] + bcoef[0];

    float v = logit;
#pragma unroll
    for (int o = 16; o > 0; o >>= 1) v = fmaxf(v, __shfl_xor_sync(0xffffffffu, v, o));
    if ((tid & 31) == 0) redbuf[tid >> 5] = v;
    __syncthreads();
    float mx = redbuf[0];
#pragma unroll
    for (int i = 1; i < 8; i++) mx = fmaxf(mx, redbuf[i]);

    float e = expf(logit - mx);
    v = e;
#pragma unroll
    for (int o = 16; o > 0; o >>= 1) v += __shfl_xor_sync(0xffffffffu, v, o);
    __syncthreads();
    if ((tid & 31) == 0) redbuf[tid >> 5] = v;
    __syncthreads();
    float s = 0.f;
#pragma unroll
    for (int i = 0; i < 8; i++) s += redbuf[i];
    attn[tid] = e / s;
    __syncthreads();

    const float* cp = &cat[(size_t)bi * 65536 + tid];
    float acc = 0.f;
#pragma unroll 8
    for (int j = 0; j < 256; j++) acc += attn[j] * cp[(size_t)j * 256];
    g_resid[row] = acc;
}

// ===========================================================================
// out: nodes + relu(resid @ W_out + b_out). BM=32 BN=64, grid (32,4)
__global__ void k_out(const float* __restrict__ nodes, const float* __restrict__ Wout,
                      const float* __restrict__ b_out, float* __restrict__ outn) {
    __shared__ float As[16][32];
    __shared__ float Bs[16][64];
    int tid = threadIdx.x;
    int tx = tid & 15, ty = tid >> 4;
    int row0 = blockIdx.x * 32;
    int n0   = blockIdx.y * 64;
    float c[2][4] = {};
    for (int k0 = 0; k0 < 256; k0 += 16) {
        {
            int f = tid;
            if (f < 128) {
                int r = f >> 2, kq = f & 3;
                float4 v = *(const float4*)&g_resid[(size_t)(row0 + r) * 256 + k0 + kq * 4];
                As[kq*4+0][r] = v.x; As[kq*4+1][r] = v.y; As[kq*4+2][r] = v.z; As[kq*4+3][r] = v.w;
            }
        }
        {
            int k = tid >> 4, nq = tid & 15;
            *(float4*)&Bs[k][nq*4] = *(const float4*)&Wout[(size_t)(k0 + k) * 256 + n0 + nq * 4];
        }
        __syncthreads();
#pragma unroll
        for (int k = 0; k < 16; k++) {
            float a0 = As[k][ty*2], a1 = As[k][ty*2+1];
            float bb[4];
            *(float4*)bb = *(float4*)&Bs[k][tx*4];
#pragma unroll
            for (int j = 0; j < 4; j++) { c[0][j] += a0 * bb[j]; c[1][j] += a1 * bb[j]; }
        }
        __syncthreads();
    }
#pragma unroll
    for (int i = 0; i < 2; i++) {
        int row = row0 + ty*2 + i;
#pragma unroll
        for (int j = 0; j < 4; j++) {
            int n = n0 + tx*4 + j;
            float v = fmaxf(c[i][j] + b_out[n], 0.f);
            outn[(size_t)row * 256 + n] = nodes[(size_t)row * 256 + n] + v;
        }
    }
}

// ===========================================================================
extern "C" void kernel_launch(void* const* d_in, const int* in_sizes, int n_in,
                              void* d_out, int out_size) {
    const float* nodes = (const float*)d_in[0];
    const float* edges = (const float*)d_in[1];
    const float* aux   = (const float*)d_in[2];
    // d_in[3] = nums (unused)
    const float* Win   = (const float*)d_in[4];
    const float* b_in  = (const float*)d_in[5];
    const float* Wcoef = (const float*)d_in[6];
    const float* bcoef = (const float*)d_in[7];
    const float* Wout  = (const float*)d_in[8];
    const float* b_out = (const float*)d_in[9];

    float* out_nodes = (float*)d_out;                    // [4,256,256]
    float* out_cat   = out_nodes + (size_t)BIv * Dv;     // [4,256,256,256]

    cudaFuncSetAttribute(k_main, cudaFuncAttributeMaxDynamicSharedMemorySize,
                         SMEM_MAIN_BYTES);

    k_prep   <<<256, 256>>>(Win);
    k_s12    <<<dim3(16, 8), 256>>>(nodes, Win, b_in);
    k_main   <<<4096, 256, SMEM_MAIN_BYTES>>>(edges, Wcoef, out_cat);
    k_softmax<<<1024, 256>>>(aux, bcoef, out_cat);
    k_out    <<<dim3(32, 4), 256>>>(nodes, Wout, b_out, out_nodes);
}